// round 11
// baseline (speedup 1.0000x reference)
#include <cuda_runtime.h>
#include <cuda_bf16.h>
#include <cstdint>

// Problem constants
#define BB   64     // batch
#define NP   900    // predictions (columns)
#define NCLS 128    // classes
#define MT   64     // targets (rows)
#define KC   8      // corners
#define INF_F 1000000000.0f

#define TLSA 128    // threads per LSA block (4 warps)
#define NPK  8      // ceil(900/128) columns per thread (tid<4 have 8, rest 7)
#define NTILE 32    // n-tile per cost block
#define MAXSLOT 72  // assigned columns never exceed MT=64

// Transposed cost scratch: CT[b][m][n], contiguous in n for fast row reads in LSA.
__device__ float g_CT[(size_t)BB * MT * NP];
// Per-(b,m) INVERTED packed row min: ~((fenc(value)<<32) | n). Zero-initialized;
// atomicMax over inverted == atomicMin over packed. lsa resets to 0 at end.
__device__ unsigned long long g_rowmin[BB * MT];

// ---------------------------------------------------------------------------
// Order-preserving float <-> u32 encoding for unsigned-min reductions.
// ---------------------------------------------------------------------------
__device__ __forceinline__ unsigned fenc(float f) {
    unsigned u = __float_as_uint(f);
    return u ^ (unsigned)(((int)u >> 31) | 0x80000000);
}
__device__ __forceinline__ float fdec(unsigned e) {
    unsigned u = (e & 0x80000000u) ? (e ^ 0x80000000u) : ~e;
    return __uint_as_float(u);
}

// ---------------------------------------------------------------------------
// Kernel 1: cost matrix. Block = (one b, 32 n), 4 warps x 8 n each.
// outC[b][n][m] coalesced; CT[b][m][n] via smem transpose (coalesced rows);
// fused per-row packed min via smem scan (tid<64) + one inverted atomicMax.
// ---------------------------------------------------------------------------
__global__ __launch_bounds__(128)
void cost_kernel(const float* __restrict__ logits,
                 const float* __restrict__ corners,
                 const int*   __restrict__ labels,
                 const float* __restrict__ boxes,
                 float* __restrict__ outC) {
    const int b    = blockIdx.y;
    const int n0   = blockIdx.x * NTILE;
    const int lane = threadIdx.x & 31;
    const int wid  = threadIdx.x >> 5;

    __shared__ float tile[MT][NTILE + 1];
    __shared__ float sh_probs[4][NCLS];
    __shared__ float sh_cen[4][3];
    __shared__ int   sh_lab[MT];
    __shared__ float sh_box[MT][3];

    if (threadIdx.x < MT) {
        sh_lab[threadIdx.x] = labels[b * MT + threadIdx.x];
        const float* bx = boxes + ((size_t)b * MT + threadIdx.x) * 7;
        sh_box[threadIdx.x][0] = bx[0];
        sh_box[threadIdx.x][1] = bx[1];
        sh_box[threadIdx.x][2] = bx[2];
    }
    __syncthreads();

    #pragma unroll
    for (int q = 0; q < 8; q++) {
        int n = n0 + wid * 8 + q;
        if (n < NP) {
            const float* lg = logits + ((size_t)b * NP + n) * NCLS;
            float l0 = lg[lane], l1 = lg[lane + 32], l2 = lg[lane + 64], l3 = lg[lane + 96];
            float mx = fmaxf(fmaxf(l0, l1), fmaxf(l2, l3));
            #pragma unroll
            for (int o = 16; o; o >>= 1) mx = fmaxf(mx, __shfl_xor_sync(0xffffffffu, mx, o));
            float e0 = expf(l0 - mx), e1 = expf(l1 - mx), e2 = expf(l2 - mx), e3 = expf(l3 - mx);
            float s = e0 + e1 + e2 + e3;
            #pragma unroll
            for (int o = 16; o; o >>= 1) s += __shfl_xor_sync(0xffffffffu, s, o);
            sh_probs[wid][lane]      = e0 / s;
            sh_probs[wid][lane + 32] = e1 / s;
            sh_probs[wid][lane + 64] = e2 / s;
            sh_probs[wid][lane + 96] = e3 / s;

            const float* cr = corners + ((size_t)b * NP + n) * (KC * 3);
            if (lane < 3) {
                float sum = 0.0f;
                #pragma unroll
                for (int k = 0; k < KC; k++) sum += cr[k * 3 + lane];
                sh_cen[wid][lane] = sum * 0.125f;
            }
            __syncwarp();
            float cx = sh_cen[wid][0], cy = sh_cen[wid][1], cz = sh_cen[wid][2];

            #pragma unroll
            for (int t = 0; t < 2; t++) {
                int m = lane + t * 32;
                float cc = -sh_probs[wid][sh_lab[m]];
                float dx = cx - sh_box[m][0], dy = cy - sh_box[m][1], dz = cz - sh_box[m][2];
                float c = cc + 5.0f * sqrtf(dx * dx + dy * dy + dz * dz);
                outC[((size_t)b * NP + n) * MT + m] = c;
                tile[m][n - n0] = c;
            }
        }
    }
    __syncthreads();

    // coalesced CT writes: warp writes a 128B row segment per iteration
    {
        const int  n   = n0 + lane;
        const bool nok = (n < NP);
        #pragma unroll
        for (int r = 0; r < 16; r++) {
            int m = wid * 16 + r;
            if (nok) g_CT[((size_t)b * MT + m) * NP + n] = tile[m][lane];
        }
    }

    // fused per-row packed min: tid<64 scans its row of the tile.
    if (threadIdx.x < MT) {
        const int m    = threadIdx.x;
        const int cmax = (NP - n0 < NTILE) ? (NP - n0) : NTILE;
        unsigned long long x = 0xFFFFFFFFFFFFFFFFull;
        #pragma unroll
        for (int c = 0; c < NTILE; c++) {
            if (c < cmax) {
                unsigned long long y =
                    ((unsigned long long)fenc(tile[m][c]) << 32) | (unsigned)(n0 + c);
                if (y < x) x = y;
            }
        }
        atomicMax(&g_rowmin[b * MT + m], ~x);
    }
}

// ---------------------------------------------------------------------------
// Kernel 2: JV LSA, slot architecture. One block (128 thr, 4 warps) per batch.
// Assigned columns (<=64) live in compact slots; thread t<nslots owns slot t.
// Free columns have v==0 forever and are scanned with a 3-register running
// min (value, j, way). Greedy prefill from fused row mins; exact shortest-
// augmenting-path phases for collided rows only.
// ---------------------------------------------------------------------------
__global__ __launch_bounds__(TLSA, 1)
void lsa_kernel(float* __restrict__ out) {
    const int b    = blockIdx.x;
    const int tid  = threadIdx.x;
    const int lane = tid & 31;
    const int wid  = tid >> 5;

    __shared__ int                scol_sh[MAXSLOT];   // slot -> column (1-based)
    __shared__ int                spi_sh[MAXSLOT];    // slot -> row p (1-based)
    __shared__ float              su_sh[MAXSLOT];     // slot -> u of its row
    __shared__ float              sv_sh[MAXSLOT];     // slot -> column dual v
    __shared__ int                map_sh[NP + 1];     // column -> slot or -1
    __shared__ int                way_sh[NP + 1];
    __shared__ float              umin_sh[MT];
    __shared__ int                jmin_sh[MT];
    __shared__ int                ua_sh[MT];
    __shared__ int                nua_sh, nslots_sh;
    __shared__ unsigned long long redbuf[2][4];
    __shared__ unsigned long long pubuf[2][4];

    for (int j = tid; j <= NP; j += TLSA) map_sh[j] = -1;
    if (tid < MT) {
        unsigned long long x = ~g_rowmin[b * MT + tid];
        umin_sh[tid] = fdec((unsigned)(x >> 32));
        jmin_sh[tid] = (int)(unsigned)x;           // 0-based column
    }

    const float* CT = g_CT + (size_t)b * MT * NP;

    // fire-and-forget L1 prime: 1800 x 128B lines, ~14 prefetches per thread
    {
        const char* base = (const char*)CT;
        const int nlines = (MT * NP * 4 + 127) / 128;
        for (int i = tid; i < nlines; i += TLSA) {
            asm volatile("prefetch.global.L1 [%0];" :: "l"(base + (size_t)i * 128));
        }
    }
    __syncthreads();

    if (tid == 0) {
        // greedy prefill: rows to free argmin columns; losers to worklist
        int nun = 0, ns = 0;
        for (int i = 0; i < MT; i++) {
            int j1 = jmin_sh[i] + 1;
            if (map_sh[j1] < 0) {
                map_sh[j1] = ns;
                scol_sh[ns] = j1;
                spi_sh[ns]  = i + 1;
                su_sh[ns]   = umin_sh[i];
                sv_sh[ns]   = 0.0f;
                ns++;
            } else ua_sh[nun++] = i + 1;
        }
        nua_sh = nun; nslots_sh = ns;
    }
    __syncthreads();

    const int nua   = nua_sh;
    const int jbase = 1 + tid;
    const bool v7   = (tid < NP - 7 * TLSA);   // tid < 4 -> k=7 valid

    // ---- exact shortest-augmenting-path phases ----
    for (int t = 0; t < nua; t++) {
        const int i1  = ua_sh[t];
        const int nsl = nslots_sh;

        // slot-owner registers
        const bool hasslot = (tid < nsl);
        int   s_col = 0, sp_reg = 0;
        float su_reg = 0.0f, sv_reg = 0.0f, smv = INF_F;
        bool  used = false;
        if (hasslot) {
            s_col  = scol_sh[tid];
            sp_reg = spi_sh[tid];
            su_reg = su_sh[tid];
            sv_reg = sv_sh[tid];
        }
        // per-phase assigned-column mask for the free stream
        unsigned amask = 0;
        #pragma unroll
        for (int k = 0; k < NPK; k++) {
            bool valid = (k < NPK - 1) | v7;
            if (valid && map_sh[jbase + TLSA * k] >= 0) amask |= 1u << k;
        }

        float fval = INF_F; int fj = 0x7FFFFFFF; int fway = 0;
        float u0col = umin_sh[i1 - 1];
        float pend  = 0.0f;
        float u0    = u0col;
        int   j0    = 0, i0 = i1;

        for (int it = 0; it < MT + 8; it++) {
            if (i0 == 0) break;

            const float* rp = CT + (size_t)(i0 - 1) * NP + tid;
            float cvals[NPK];
            #pragma unroll
            for (int k = 0; k < NPK; k++) {
                bool valid = (k < NPK - 1) | v7;
                if (valid) cvals[k] = rp[TLSA * k];
            }

            // free-column stream: v==0, running (val, j, way) min
            fval -= pend;
            #pragma unroll
            for (int k = 0; k < NPK; k++) {
                bool valid = (k < NPK - 1) | v7;
                if (valid && !((amask >> k) & 1)) {
                    int   j   = jbase + TLSA * k;
                    float cur = cvals[k] - u0;
                    if (cur < fval || (cur == fval && j < fj)) {
                        fval = cur; fj = j; fway = j0;
                    }
                }
            }

            // assigned-slot full update (one slot per thread)
            unsigned long long slotpk = 0xFFFFFFFFFFFFFFFFull;
            if (hasslot) {
                if (used) { sv_reg -= pend; su_reg += pend; }
                else      smv -= pend;
                if (s_col == j0) used = true;
                float c   = CT[(size_t)(i0 - 1) * NP + (s_col - 1)];
                float cur = c - u0 - sv_reg;
                if (!used && cur < smv) { smv = cur; way_sh[s_col] = j0; }
                float mv = used ? INF_F : smv;
                slotpk = ((unsigned long long)fenc(mv) << 32) | (unsigned)s_col;
            }
            u0col += pend;

            // merge candidates, reduce (value then column)
            unsigned long long freepk =
                ((unsigned long long)fenc(fval) << 32) | (unsigned)fj;
            unsigned long long myb;
            int   bp; float bu;
            if (slotpk < freepk) { myb = slotpk; bp = sp_reg; bu = su_reg; }
            else                 { myb = freepk; bp = 0;      bu = 0.0f;   }

            unsigned bestenc = (unsigned)(myb >> 32);
            unsigned wenc = __reduce_min_sync(0xffffffffu, bestenc);
            unsigned ball = __ballot_sync(0xffffffffu, bestenc == wenc);
            if (lane == __ffs(ball) - 1) {
                redbuf[it & 1][wid] = myb;
                pubuf [it & 1][wid] = ((unsigned long long)(unsigned)bp << 32)
                                      | __float_as_uint(bu);
            }
            __syncthreads();

            const unsigned long long* rb = redbuf[it & 1];
            const unsigned long long* pb = pubuf[it & 1];
            unsigned long long b0 = rb[0], b1 = rb[1], b2 = rb[2], b3 = rb[3];
            unsigned long long q0 = pb[0], q1 = pb[1], q2 = pb[2], q3 = pb[3];
            if (b1 < b0) { b0 = b1; q0 = q1; }
            if (b3 < b2) { b2 = b3; q2 = q3; }
            if (b2 < b0) { b0 = b2; q0 = q2; }

            j0   = (int)(unsigned)b0;
            pend = fdec((unsigned)(b0 >> 32));
            i0   = (int)(q0 >> 32);
            u0   = __uint_as_float((unsigned)q0);
        }

        // flush final delta; publish slot duals; terminal way
        if (hasslot) {
            if (used) { sv_reg -= pend; su_reg += pend; }
            sv_sh[tid] = sv_reg;
            su_sh[tid] = su_reg;
        }
        u0col += pend;
        if (fj == j0) way_sh[j0] = fway;   // unique owner of terminal free col
        __syncthreads();

        // backtrack (tid 0): new slot for terminal col, shift rows along path
        if (tid == 0) {
            int jj   = j0;
            int snew = nslots_sh;
            scol_sh[snew] = jj;
            sv_sh[snew]   = 0.0f;          // free col had v == 0
            map_sh[jj]    = snew;
            nslots_sh     = snew + 1;
            int scur = snew;
            for (int s = 0; s < MT + 8; s++) {
                int jp = way_sh[jj];
                if (jp == 0) { spi_sh[scur] = i1; su_sh[scur] = u0col; break; }
                int sp2 = map_sh[jp];
                spi_sh[scur] = spi_sh[sp2];
                su_sh[scur]  = su_sh[sp2];
                scur = sp2; jj = jp;
            }
        }
        __syncthreads();
    }

    // outputs: pred_idx (value-cast float), tgt_idx
    float* predf = out + (size_t)BB * NP * MT;
    float* tgtf  = predf + (size_t)BB * MT;
    if (tid < nslots_sh)
        predf[b * MT + (spi_sh[tid] - 1)] = (float)(scol_sh[tid] - 1);
    for (int m = tid; m < MT; m += TLSA) tgtf[b * MT + m] = (float)m;

    // reset row-min table for the next call (idempotent state)
    if (tid < MT) g_rowmin[b * MT + tid] = 0ull;
}

// ---------------------------------------------------------------------------
extern "C" void kernel_launch(void* const* d_in, const int* in_sizes, int n_in,
                              void* d_out, int out_size) {
    const float* logits  = (const float*)d_in[0];   // [64, 900, 128]
    const float* corners = (const float*)d_in[1];   // [64, 900, 8, 3]
    const int*   labels  = (const int*)  d_in[2];   // [64, 64]
    const float* boxes   = (const float*)d_in[3];   // [64, 64, 7]
    float* out = (float*)d_out;

    (void)in_sizes; (void)n_in; (void)out_size;

    dim3 cgrid((NP + NTILE - 1) / NTILE, BB);       // 29 x 64
    cost_kernel<<<cgrid, 128>>>(logits, corners, labels, boxes, out);

    lsa_kernel<<<BB, TLSA>>>(out);
}